// round 10
// baseline (speedup 1.0000x reference)
#include <cuda_runtime.h>
#include <cstdint>

#define LMAX  6
#define BATCH 1024
#define F     64
#define IR    455
#define NROT  64
#define FS    (F * IR)   // 29120 floats per batch element

// Raw packed pre-scaled weights W_l[k, n] (f32), k=(f*d+u), n=(g*d+v).
__device__ float g_W[4096 * 455];
// Fragment-ordered bf16x2 hi/lo planes of W.
// Per l (offset 4096*off[l] u32): [ktile(4d)][bn(d)][plane(2)][wt(2)][c(2)][lane(32)][j(4)]
__device__ uint32_t g_Wf[4096 * 455];

// Tile decode tables, ordered l = 6..0 (largest K first).
__constant__ int c2_cnt[7] = {728, 528, 360, 224, 120, 48, 8}; // 8d * ceil(d/2)
__constant__ int c_d[7]    = {13, 11, 9, 7, 5, 3, 1};
__constant__ int c_off[7]  = {286, 165, 84, 35, 10, 1, 0};

// ---------------------------------------------------------------------------
// helpers
// ---------------------------------------------------------------------------
__device__ __forceinline__ uint32_t pack_bf16x2(float lo_e, float hi_e) {
    uint32_t r;
    asm("cvt.rn.bf16x2.f32 %0, %1, %2;" : "=r"(r) : "f"(hi_e), "f"(lo_e));
    return r;
}
__device__ __forceinline__ float bf16_lo_f32(uint32_t p) { return __uint_as_float(p << 16); }
__device__ __forceinline__ float bf16_hi_f32(uint32_t p) { return __uint_as_float(p & 0xffff0000u); }

__device__ __forceinline__ uint32_t split_pack(float e0, float e1, uint32_t& lo_out) {
    uint32_t hi = pack_bf16x2(e0, e1);
    lo_out = pack_bf16x2(e0 - bf16_lo_f32(hi), e1 - bf16_hi_f32(hi));
    return hi;
}

__device__ __forceinline__ void mma_bf16(float c[4],
                                         const uint32_t a[4],
                                         const uint32_t b[2])
{
    asm volatile(
        "mma.sync.aligned.m16n8k16.row.col.f32.bf16.bf16.f32 "
        "{%0,%1,%2,%3}, {%4,%5,%6,%7}, {%8,%9}, {%0,%1,%2,%3};"
        : "+f"(c[0]), "+f"(c[1]), "+f"(c[2]), "+f"(c[3])
        : "r"(a[0]), "r"(a[1]), "r"(a[2]), "r"(a[3]), "r"(b[0]), "r"(b[1]));
}

__device__ __forceinline__ void cp16(uint32_t s, const void* g) {
    asm volatile("cp.async.cg.shared.global [%0], [%1], 16;" :: "r"(s), "l"(g));
}
__device__ __forceinline__ void cp_commit() { asm volatile("cp.async.commit_group;"); }
template <int W>
__device__ __forceinline__ void cp_wait() { asm volatile("cp.async.wait_group %0;" :: "n"(W)); }

// ---------------------------------------------------------------------------
// Kernel 1: psi GEMM.  C[fg, i] = sum_r w[fg, r] * D[r, i], scattered into g_W.
// grid = (8, 64)
// ---------------------------------------------------------------------------
__global__ void __launch_bounds__(256) build_w2_kernel(const float* __restrict__ D,
                                                       const float* __restrict__ w)
{
    const int dtab[7] = {1, 3, 5, 7, 9, 11, 13};
    const int otab[7] = {0, 1, 10, 35, 84, 165, 286};

    __shared__ float Wsh[64][68];
    __shared__ float Dsh[64][68];

    const int t   = threadIdx.x;
    const int fg0 = blockIdx.y * 64;
    const int i0  = blockIdx.x * 64;

    for (int idx = t; idx < 4096; idx += 256) {
        int row = idx >> 6, r = idx & 63;
        Wsh[r][row] = w[(fg0 + row) * 64 + r];
    }
    for (int idx = t; idx < 4096; idx += 256) {
        int r = idx >> 6, c = idx & 63;
        int i = i0 + c;
        Dsh[r][c] = (i < IR) ? D[r * IR + i] : 0.0f;
    }
    __syncthreads();

    const int ty = t >> 4, tx = t & 15;
    float acc[4][4] = {};

#pragma unroll 4
    for (int r = 0; r < 64; ++r) {
        float4 a4 = *(const float4*)&Wsh[r][ty * 4];
        float4 b4 = *(const float4*)&Dsh[r][tx * 4];
        float av[4] = {a4.x, a4.y, a4.z, a4.w};
        float bv[4] = {b4.x, b4.y, b4.z, b4.w};
#pragma unroll
        for (int i = 0; i < 4; ++i)
#pragma unroll
            for (int j = 0; j < 4; ++j)
                acc[i][j] += av[i] * bv[j];
    }

#pragma unroll
    for (int j = 0; j < 4; ++j) {
        const int i = i0 + tx * 4 + j;
        if (i >= IR) continue;
        int l = 0;
#pragma unroll
        for (int q = 1; q < 7; ++q)
            if (i >= otab[q]) l = q;
        const int d = dtab[l], off = otab[l];
        const int jj = i - off;
        const int u = jj / d, v = jj - u * d;
        const float scale = rsqrtf((float)d) * (1.0f / 64.0f);
        const int base = 4096 * off;
        const int N = 64 * d;
#pragma unroll
        for (int i4 = 0; i4 < 4; ++i4) {
            const int fg = fg0 + ty * 4 + i4;
            const int f = fg >> 6, gg = fg & 63;
            g_W[base + (f * d + u) * N + gg * d + v] = scale * acc[i4][j];
        }
    }
}

// ---------------------------------------------------------------------------
// Kernel 1b: pack g_W into fragment-ordered bf16x2 hi/lo planes (g_Wf).
// grid = (2704, 7), guard idx < 4096*d*d.
// ---------------------------------------------------------------------------
__global__ void __launch_bounds__(256) pack_w2_kernel()
{
    const int dtab[7] = {1, 3, 5, 7, 9, 11, 13};
    const int otab[7] = {0, 1, 10, 35, 84, 165, 286};

    const int l = blockIdx.y;
    const int d = dtab[l];
    const int off = otab[l];
    const int N = 64 * d;
    const int tot = 4096 * d * d;
    const int idx = blockIdx.x * 256 + threadIdx.x;
    if (idx >= tot) return;

    const int j    = idx & 3;
    const int lane = (idx >> 2) & 31;
    const int c    = (idx >> 7) & 1;
    const int wt   = (idx >> 8) & 1;
    const int pl   = (idx >> 9) & 1;
    const int rest = idx >> 10;
    const int bn   = rest % d;
    const int kt   = rest / d;

    const int g  = lane >> 2;
    const int tg = lane & 3;
    const int k2 = kt * 8 + tg + 4 * (j & 1);
    const int n  = bn * 64 + wt * 32 + (2 * c + (j >> 1)) * 8 + g;

    const float e0 = g_W[4096 * off + (2 * k2) * N + n];
    const float e1 = g_W[4096 * off + (2 * k2 + 1) * N + n];
    uint32_t lo;
    uint32_t hi = split_pack(e0, e1, lo);
    g_Wf[4096 * off + idx] = pl ? lo : hi;
}

// ---------------------------------------------------------------------------
// Kernel 2: fused GEMM, 128x128 block (two 64-col bn groups), 512 threads,
// 16 warps of 32x32. bf16x2-split, fragment-ordered operands, direct-LDG A,
// double-buffered smem, one __syncthreads per k16 tile.
// ---------------------------------------------------------------------------
__global__ void __launch_bounds__(512) so3_v5_kernel(const float* __restrict__ x,
                                                     float* __restrict__ out)
{
    // ---- decode (l, bm, half) ----
    int rem = blockIdx.x;
    int li = 0;
#pragma unroll
    for (int q = 0; q < 6; ++q)
        if (rem >= c2_cnt[li]) { rem -= c2_cnt[li]; li++; }
    const int d    = c_d[li];
    const int offl = c_off[li];
    const int hd   = (d + 1) >> 1;
    const int half = rem % hd;
    const int bm   = rem / hd;
    const int bn0  = 2 * half;
    const bool valid1 = (bn0 + 1 < d);

    const int K = 64 * d;

    // A fragments: [stage][(mt*32+lane)*2 + kc] -> (h_j0, h_j1, l_j0, l_j1)
    __shared__ __align__(16) uint4    AF[2][512];    // 16 KB
    __shared__ __align__(16) uint32_t BF[2][2048];   // 16 KB  [stage][group(2)][1024]

    const int t    = threadIdx.x;
    const int wid  = t >> 5;
    const int lane = t & 31;
    const int g    = lane >> 2;
    const int tg   = lane & 3;
    const int wmi  = wid & 3;          // warp m index (32-row tiles)
    const int wn   = wid >> 2;         // 0..3
    const int gw   = wn >> 1;          // column group 0/1
    const int wnn  = wn & 1;           // 32-col half within group
    const bool active = (gw == 0) || valid1;

    // ---- A gather mapping: rows {m, m+8}, kslots {2tg+8kc, 2tg+8kc+1} ----
    const int kc  = t >> 8;            // 0/1
    const int r8  = (t >> 5) & 7;      // m-16-tile index
    const int m   = r8 * 16 + g;
    const int gr0 = bm * 128 + m;
    const int b0_ = gr0 / d;
    const int b8_ = (gr0 + 8) / d;
    const float* base0 = x + b0_ * FS + offl + (gr0 - b0_ * d);
    const float* base8 = x + b8_ * FS + offl + ((gr0 + 8) - b8_ * d);

    const int q16 = 16 / d;
    const int r16 = 16 - q16 * d;
    int uA[2], offA[2];
    {
        const int k0 = 2 * tg + 8 * kc;
#pragma unroll
        for (int j = 0; j < 2; ++j) {
            const int k = k0 + j;
            const int f = k / d;
            uA[j]   = k - f * d;
            offA[j] = f * IR + uA[j] * d;
        }
    }

    // ---- B staging: each thread copies 16B of its group's 4KB chunk ----
    const int gB   = t >> 8;           // group this thread stages
    const int tid8 = t & 255;
    int bnB = bn0 + gB;
    if (bnB >= d) bnB = bn0;           // odd-d tail: duplicate group0 (unused)
    const uint32_t* Wsrc = g_Wf + 4096 * offl + bnB * 1024 + tid8 * 4;
    const int WstepB = d * 1024;       // u32 per k16 tile

    const uint32_t bf_b = (uint32_t)__cvta_generic_to_shared(&BF[0][0]);
    const uint32_t bsB  = bf_b + (uint32_t)(gB * 1024 + tid8 * 4) * 4;

    float acc[2][4][4] = {};
    float v[4];

    // ---- prologue: LDG A(0), cp.async B(0) ----
    v[0] = base0[offA[0]]; v[1] = base0[offA[1]];
    v[2] = base8[offA[0]]; v[3] = base8[offA[1]];
#pragma unroll
    for (int j = 0; j < 2; ++j) {
        uA[j] += r16; offA[j] += q16 * IR + r16 * d;
        if (uA[j] >= d) { uA[j] -= d; offA[j] += IR - d * d; }
    }
    cp16(bsB, Wsrc);
    cp_commit();
    Wsrc += WstepB;

    const int ntiles = K >> 4;
    for (int it = 0; it < ntiles; ++it) {
        const int s = it & 1;

        // ---- 1. split + STS current A into buffer s ----
        {
            uint32_t l0, l1;
            uint32_t h0 = split_pack(v[0], v[1], l0);   // row m
            uint32_t h1 = split_pack(v[2], v[3], l1);   // row m+8
            AF[s][(r8 * 32 + lane) * 2 + kc] = make_uint4(h0, h1, l0, l1);
        }

        // ---- 2. prefetch A(it+1) ----
        if (it + 1 < ntiles) {
            v[0] = base0[offA[0]]; v[1] = base0[offA[1]];
            v[2] = base8[offA[0]]; v[3] = base8[offA[1]];
#pragma unroll
            for (int j = 0; j < 2; ++j) {
                uA[j] += r16; offA[j] += q16 * IR + r16 * d;
                if (uA[j] >= d) { uA[j] -= d; offA[j] += IR - d * d; }
            }
        }

        // ---- 3. wait B(it), barrier ----
        cp_wait<0>();
        __syncthreads();

        // ---- 4. issue B(it+1) into stage s^1 ----
        if (it + 1 < ntiles) {
            cp16(bsB + (s ^ 1) * 8192, Wsrc);
            cp_commit();
            Wsrc += WstepB;
        }

        // ---- 5. fragments + 24 MMA on buffer s ----
        if (active) {
            uint32_t ah[2][4], al[2][4], bh[4][2], bl[4][2];
#pragma unroll
            for (int mi = 0; mi < 2; ++mi) {
                const int mt = wmi * 2 + mi;
                uint4 u0 = AF[s][(mt * 32 + lane) * 2 + 0];
                uint4 u1 = AF[s][(mt * 32 + lane) * 2 + 1];
                ah[mi][0] = u0.x; ah[mi][1] = u0.y; ah[mi][2] = u1.x; ah[mi][3] = u1.y;
                al[mi][0] = u0.z; al[mi][1] = u0.w; al[mi][2] = u1.z; al[mi][3] = u1.w;
            }
            const uint32_t* Bg = &BF[s][gw * 1024];
#pragma unroll
            for (int p = 0; p < 2; ++p) {
                uint32_t (*bf)[2] = p ? bl : bh;
                uint4 q0 = *(const uint4*)&Bg[p * 512 + wnn * 256 + lane * 4];
                uint4 q1 = *(const uint4*)&Bg[p * 512 + wnn * 256 + 128 + lane * 4];
                bf[0][0] = q0.x; bf[0][1] = q0.y; bf[1][0] = q0.z; bf[1][1] = q0.w;
                bf[2][0] = q1.x; bf[2][1] = q1.y; bf[3][0] = q1.z; bf[3][1] = q1.w;
            }
#pragma unroll
            for (int mi = 0; mi < 2; ++mi)
#pragma unroll
                for (int ni = 0; ni < 4; ++ni) {
                    mma_bf16(acc[mi][ni], ah[mi], bh[ni]);   // hi*hi
                    mma_bf16(acc[mi][ni], ah[mi], bl[ni]);   // hi*lo
                    mma_bf16(acc[mi][ni], al[mi], bh[ni]);   // lo*hi
                }
        }
    }

    // ---- epilogue: scatter into out[b, g, off + v*d + m] ----
    if (active) {
#pragma unroll
        for (int mi = 0; mi < 2; ++mi) {
#pragma unroll
            for (int cr = 0; cr < 2; ++cr) {
                const int row = bm * 128 + wmi * 32 + mi * 16 + g + cr * 8;
                const int b = row / d;
                const int mm = row - b * d;
                float* ob = out + b * FS + offl + mm;
#pragma unroll
                for (int ni = 0; ni < 4; ++ni) {
#pragma unroll
                    for (int cc = 0; cc < 2; ++cc) {
                        const int col = (bn0 + gw) * 64 + wnn * 32 + ni * 8 + tg * 2 + cc;
                        const int gg = col / d;
                        const int vv = col - gg * d;
                        ob[gg * IR + vv * d] = acc[mi][ni][cr * 2 + cc];
                    }
                }
            }
        }
    }
}

// ---------------------------------------------------------------------------
extern "C" void kernel_launch(void* const* d_in, const int* in_sizes, int n_in,
                              void* d_out, int out_size)
{
    const float* x = nullptr;
    const float* D = nullptr;
    const float* w = nullptr;
    for (int i = 0; i < n_in; ++i) {
        if (in_sizes[i] == NROT * IR)         D = (const float*)d_in[i];
        else if (in_sizes[i] == F * F * NROT) w = (const float*)d_in[i];
        else                                  x = (const float*)d_in[i];
    }
    float* out = (float*)d_out;

    build_w2_kernel<<<dim3(8, 64), 256>>>(D, w);
    pack_w2_kernel<<<dim3(2704, LMAX + 1), 256>>>();
    // Total blocks: sum over l of 8d * ceil(d/2) = 2016
    so3_v5_kernel<<<2016, 512>>>(x, out);
}

// round 11
// speedup vs baseline: 1.3842x; 1.3842x over previous
#include <cuda_runtime.h>
#include <cstdint>

#define LMAX  6
#define BATCH 1024
#define F     64
#define IR    455
#define NROT  64
#define FS    (F * IR)   // 29120 floats per batch element

// Raw packed pre-scaled weights W_l[k, n] (f32), k=(f*d+u), n=(g*d+v).
__device__ float g_W[4096 * 455];
// Fragment-ordered bf16x2 hi/lo planes of W.
// Per l (offset 4096*off[l] u32): [ktile(4d)][bn(d)][plane(2)][wt(2)][c(2)][lane(32)][j(4)]
__device__ uint32_t g_Wf[4096 * 455];

// Tile decode tables, ordered l = 6..0 (largest K first).
__constant__ int c_cnt[7]  = {1352, 968, 648, 392, 200, 72, 8}; // 8*d*d
__constant__ int c_d[7]    = {13, 11, 9, 7, 5, 3, 1};
__constant__ int c_off[7]  = {286, 165, 84, 35, 10, 1, 0};

// ---------------------------------------------------------------------------
// helpers
// ---------------------------------------------------------------------------
__device__ __forceinline__ uint32_t pack_bf16x2(float lo_e, float hi_e) {
    uint32_t r;
    asm("cvt.rn.bf16x2.f32 %0, %1, %2;" : "=r"(r) : "f"(hi_e), "f"(lo_e));
    return r;
}
__device__ __forceinline__ float bf16_lo_f32(uint32_t p) { return __uint_as_float(p << 16); }
__device__ __forceinline__ float bf16_hi_f32(uint32_t p) { return __uint_as_float(p & 0xffff0000u); }

__device__ __forceinline__ uint32_t split_pack(float e0, float e1, uint32_t& lo_out) {
    uint32_t hi = pack_bf16x2(e0, e1);
    lo_out = pack_bf16x2(e0 - bf16_lo_f32(hi), e1 - bf16_hi_f32(hi));
    return hi;
}

__device__ __forceinline__ void mma_bf16(float c[4],
                                         const uint32_t a[4],
                                         const uint32_t b[2])
{
    asm volatile(
        "mma.sync.aligned.m16n8k16.row.col.f32.bf16.bf16.f32 "
        "{%0,%1,%2,%3}, {%4,%5,%6,%7}, {%8,%9}, {%0,%1,%2,%3};"
        : "+f"(c[0]), "+f"(c[1]), "+f"(c[2]), "+f"(c[3])
        : "r"(a[0]), "r"(a[1]), "r"(a[2]), "r"(a[3]), "r"(b[0]), "r"(b[1]));
}

__device__ __forceinline__ void cp16(uint32_t s, const void* g) {
    asm volatile("cp.async.cg.shared.global [%0], [%1], 16;" :: "r"(s), "l"(g));
}
__device__ __forceinline__ void cp_commit() { asm volatile("cp.async.commit_group;"); }
template <int W>
__device__ __forceinline__ void cp_wait() { asm volatile("cp.async.wait_group %0;" :: "n"(W)); }

// ---------------------------------------------------------------------------
// Kernel 1: psi GEMM.  C[fg, i] = sum_r w[fg, r] * D[r, i], scattered into g_W.
// grid = (8, 64)
// ---------------------------------------------------------------------------
__global__ void __launch_bounds__(256) build_w2_kernel(const float* __restrict__ D,
                                                       const float* __restrict__ w)
{
    const int dtab[7] = {1, 3, 5, 7, 9, 11, 13};
    const int otab[7] = {0, 1, 10, 35, 84, 165, 286};

    __shared__ float Wsh[64][68];
    __shared__ float Dsh[64][68];

    const int t   = threadIdx.x;
    const int fg0 = blockIdx.y * 64;
    const int i0  = blockIdx.x * 64;

    for (int idx = t; idx < 4096; idx += 256) {
        int row = idx >> 6, r = idx & 63;
        Wsh[r][row] = w[(fg0 + row) * 64 + r];
    }
    for (int idx = t; idx < 4096; idx += 256) {
        int r = idx >> 6, c = idx & 63;
        int i = i0 + c;
        Dsh[r][c] = (i < IR) ? D[r * IR + i] : 0.0f;
    }
    __syncthreads();

    const int ty = t >> 4, tx = t & 15;
    float acc[4][4] = {};

#pragma unroll 4
    for (int r = 0; r < 64; ++r) {
        float4 a4 = *(const float4*)&Wsh[r][ty * 4];
        float4 b4 = *(const float4*)&Dsh[r][tx * 4];
        float av[4] = {a4.x, a4.y, a4.z, a4.w};
        float bv[4] = {b4.x, b4.y, b4.z, b4.w};
#pragma unroll
        for (int i = 0; i < 4; ++i)
#pragma unroll
            for (int j = 0; j < 4; ++j)
                acc[i][j] += av[i] * bv[j];
    }

#pragma unroll
    for (int j = 0; j < 4; ++j) {
        const int i = i0 + tx * 4 + j;
        if (i >= IR) continue;
        int l = 0;
#pragma unroll
        for (int q = 1; q < 7; ++q)
            if (i >= otab[q]) l = q;
        const int d = dtab[l], off = otab[l];
        const int jj = i - off;
        const int u = jj / d, v = jj - u * d;
        const float scale = rsqrtf((float)d) * (1.0f / 64.0f);
        const int base = 4096 * off;
        const int N = 64 * d;
#pragma unroll
        for (int i4 = 0; i4 < 4; ++i4) {
            const int fg = fg0 + ty * 4 + i4;
            const int f = fg >> 6, gg = fg & 63;
            g_W[base + (f * d + u) * N + gg * d + v] = scale * acc[i4][j];
        }
    }
}

// ---------------------------------------------------------------------------
// Kernel 1b: pack g_W into fragment-ordered bf16x2 hi/lo planes (g_Wf).
// grid = (2704, 7), guard idx < 4096*d*d.
// ---------------------------------------------------------------------------
__global__ void __launch_bounds__(256) pack_w2_kernel()
{
    const int dtab[7] = {1, 3, 5, 7, 9, 11, 13};
    const int otab[7] = {0, 1, 10, 35, 84, 165, 286};

    const int l = blockIdx.y;
    const int d = dtab[l];
    const int off = otab[l];
    const int N = 64 * d;
    const int tot = 4096 * d * d;
    const int idx = blockIdx.x * 256 + threadIdx.x;
    if (idx >= tot) return;

    const int j    = idx & 3;
    const int lane = (idx >> 2) & 31;
    const int c    = (idx >> 7) & 1;
    const int wt   = (idx >> 8) & 1;
    const int pl   = (idx >> 9) & 1;
    const int rest = idx >> 10;
    const int bn   = rest % d;
    const int kt   = rest / d;

    const int g  = lane >> 2;
    const int tg = lane & 3;
    const int k2 = kt * 8 + tg + 4 * (j & 1);
    const int n  = bn * 64 + wt * 32 + (2 * c + (j >> 1)) * 8 + g;

    const float e0 = g_W[4096 * off + (2 * k2) * N + n];
    const float e1 = g_W[4096 * off + (2 * k2 + 1) * N + n];
    uint32_t lo;
    uint32_t hi = split_pack(e0, e1, lo);
    g_Wf[4096 * off + idx] = pl ? lo : hi;
}

// ---------------------------------------------------------------------------
// Kernel 2: fused GEMM, bf16x2-split, fragment-ordered operands,
// direct-LDG A staging, double-buffered smem, BK=32: one __syncthreads
// per TWO k16 sub-tiles (48 MMAs per barrier).
// Block tile 128x64, 256 threads = 8 warps (4x2 of 32x32 warp tiles).
// ---------------------------------------------------------------------------
__global__ void __launch_bounds__(256) so3_v6_kernel(const float* __restrict__ x,
                                                     float* __restrict__ out)
{
    // ---- decode (l, bm, bn) ----
    int rem = blockIdx.x;
    int li = 0;
#pragma unroll
    for (int q = 0; q < 6; ++q)
        if (rem >= c_cnt[li]) { rem -= c_cnt[li]; li++; }
    const int d    = c_d[li];
    const int offl = c_off[li];
    const int bn   = rem % d;
    const int bm   = rem / d;

    const int K = 64 * d;

    // [stage][sub][1024], 16B-stride-per-lane fragment order (conflict-free)
    __shared__ __align__(16) uint32_t AhF[2][2][1024];   // 16 KB
    __shared__ __align__(16) uint32_t AlF[2][2][1024];   // 16 KB
    __shared__ __align__(16) uint32_t BF [2][2][1024];   // 16 KB

    const int t    = threadIdx.x;
    const int wid  = t >> 5;
    const int lane = t & 31;
    const int g    = lane >> 2;
    const int tg   = lane & 3;
    const int wmi  = wid & 3;          // warp m index (32-row tiles)
    const int wt   = wid >> 2;         // warp n half (32 cols)

    // ---- direct A gather mapping: this thread's fragment slot ----
    const int m    = (t >> 5) * 16 + g;
    const int gr0  = bm * 128 + m;
    const int gr8  = gr0 + 8;
    const int b0_  = gr0 / d;
    const int b8_  = gr8 / d;
    const float* base0 = x + b0_ * FS + offl + (gr0 - b0_ * d);
    const float* base8 = x + b8_ * FS + offl + (gr8 - b8_ * d);

    const int q16 = 16 / d;
    const int r16 = 16 - q16 * d;
    const int kl[4] = {2 * tg, 2 * tg + 1, 2 * tg + 8, 2 * tg + 9};
    int uA[4], offA[4];
#pragma unroll
    for (int j = 0; j < 4; ++j) {
        const int f = kl[j] / d;
        uA[j]   = kl[j] - f * d;
        offA[j] = f * IR + uA[j] * d;
    }

    // ---- B staging ----
    const uint32_t* Wsrc = g_Wf + 4096 * offl + bn * 1024 + t * 4;
    const int WstepB = d * 1024;   // u32 per k16 sub-tile

    const uint32_t bf_b = (uint32_t)__cvta_generic_to_shared(&BF[0][0][0]);
    const uint32_t bsB  = bf_b + t * 16;

    float acc[2][4][4] = {};
    float v0[8], v1[8];

#define LOAD_A(dst)                                                     \
    do {                                                                \
        dst[0] = base0[offA[0]]; dst[1] = base0[offA[1]];               \
        dst[2] = base8[offA[0]]; dst[3] = base8[offA[1]];               \
        dst[4] = base0[offA[2]]; dst[5] = base0[offA[3]];               \
        dst[6] = base8[offA[2]]; dst[7] = base8[offA[3]];               \
        _Pragma("unroll")                                               \
        for (int j = 0; j < 4; ++j) {                                   \
            uA[j] += r16; offA[j] += q16 * IR + r16 * d;                \
            if (uA[j] >= d) { uA[j] -= d; offA[j] += IR - d * d; }      \
        }                                                               \
    } while (0)

    // ---- prologue: LDG A(0) subs 0+1, cp.async B(0) subs 0+1 ----
    LOAD_A(v0);
    LOAD_A(v1);
    cp16(bsB, Wsrc);
    cp16(bsB + 4096, Wsrc + WstepB);
    cp_commit();
    Wsrc += 2 * WstepB;

    const int ntiles = K >> 5;   // k32 tiles = 2d
    for (int it = 0; it < ntiles; ++it) {
        const int s = it & 1;

        // ---- 1. split + STS both subs into buffer s ----
        {
            uint32_t l0, l1, l2, l3;
            uint32_t h0 = split_pack(v0[0], v0[1], l0);
            uint32_t h1 = split_pack(v0[2], v0[3], l1);
            uint32_t h2 = split_pack(v0[4], v0[5], l2);
            uint32_t h3 = split_pack(v0[6], v0[7], l3);
            *(uint4*)&AhF[s][0][t * 4] = make_uint4(h0, h1, h2, h3);
            *(uint4*)&AlF[s][0][t * 4] = make_uint4(l0, l1, l2, l3);
            h0 = split_pack(v1[0], v1[1], l0);
            h1 = split_pack(v1[2], v1[3], l1);
            h2 = split_pack(v1[4], v1[5], l2);
            h3 = split_pack(v1[6], v1[7], l3);
            *(uint4*)&AhF[s][1][t * 4] = make_uint4(h0, h1, h2, h3);
            *(uint4*)&AlF[s][1][t * 4] = make_uint4(l0, l1, l2, l3);
        }

        // ---- 2. prefetch A(it+1), both subs ----
        if (it + 1 < ntiles) {
            LOAD_A(v0);
            LOAD_A(v1);
        }

        // ---- 3. wait B(it), barrier ----
        cp_wait<0>();
        __syncthreads();

        // ---- 4. issue B(it+1) into stage s^1 ----
        if (it + 1 < ntiles) {
            cp16(bsB + (s ^ 1) * 8192, Wsrc);
            cp16(bsB + (s ^ 1) * 8192 + 4096, Wsrc + WstepB);
            cp_commit();
            Wsrc += 2 * WstepB;
        }

        // ---- 5. fragments + 2x24 MMA on buffer s ----
#pragma unroll
        for (int sub = 0; sub < 2; ++sub) {
            uint32_t ah[2][4], al[2][4], bh[4][2], bl[4][2];
#pragma unroll
            for (int mi = 0; mi < 2; ++mi) {
                const int mt = wmi * 2 + mi;
                uint4 a4 = *(const uint4*)&AhF[s][sub][(mt * 32 + lane) * 4];
                ah[mi][0] = a4.x; ah[mi][1] = a4.y; ah[mi][2] = a4.z; ah[mi][3] = a4.w;
                uint4 b4 = *(const uint4*)&AlF[s][sub][(mt * 32 + lane) * 4];
                al[mi][0] = b4.x; al[mi][1] = b4.y; al[mi][2] = b4.z; al[mi][3] = b4.w;
            }
#pragma unroll
            for (int p = 0; p < 2; ++p) {
                uint32_t (*bf)[2] = p ? bl : bh;
                uint4 q0 = *(const uint4*)&BF[s][sub][p * 512 + wt * 256 + lane * 4];
                uint4 q1 = *(const uint4*)&BF[s][sub][p * 512 + wt * 256 + 128 + lane * 4];
                bf[0][0] = q0.x; bf[0][1] = q0.y; bf[1][0] = q0.z; bf[1][1] = q0.w;
                bf[2][0] = q1.x; bf[2][1] = q1.y; bf[3][0] = q1.z; bf[3][1] = q1.w;
            }
#pragma unroll
            for (int mi = 0; mi < 2; ++mi)
#pragma unroll
                for (int ni = 0; ni < 4; ++ni) {
                    mma_bf16(acc[mi][ni], ah[mi], bh[ni]);   // hi*hi
                    mma_bf16(acc[mi][ni], ah[mi], bl[ni]);   // hi*lo
                    mma_bf16(acc[mi][ni], al[mi], bh[ni]);   // lo*hi
                }
        }
        // reads of buffer s complete before the next barrier, which precedes
        // the overwrite of s two iterations later.
    }

#undef LOAD_A

    // ---- epilogue: scatter into out[b, g, off + v*d + m] ----
#pragma unroll
    for (int mi = 0; mi < 2; ++mi) {
#pragma unroll
        for (int cr = 0; cr < 2; ++cr) {
            const int row = bm * 128 + wmi * 32 + mi * 16 + g + cr * 8;
            const int b = row / d;
            const int mm = row - b * d;
            float* ob = out + b * FS + offl + mm;
#pragma unroll
            for (int ni = 0; ni < 4; ++ni) {
#pragma unroll
                for (int cc = 0; cc < 2; ++cc) {
                    const int col = bn * 64 + wt * 32 + ni * 8 + tg * 2 + cc;
                    const int gg = col / d;
                    const int vv = col - gg * d;
                    ob[gg * IR + vv * d] = acc[mi][ni][cr * 2 + cc];
                }
            }
        }
    }
}

// ---------------------------------------------------------------------------
extern "C" void kernel_launch(void* const* d_in, const int* in_sizes, int n_in,
                              void* d_out, int out_size)
{
    const float* x = nullptr;
    const float* D = nullptr;
    const float* w = nullptr;
    for (int i = 0; i < n_in; ++i) {
        if (in_sizes[i] == NROT * IR)         D = (const float*)d_in[i];
        else if (in_sizes[i] == F * F * NROT) w = (const float*)d_in[i];
        else                                  x = (const float*)d_in[i];
    }
    float* out = (float*)d_out;

    build_w2_kernel<<<dim3(8, 64), 256>>>(D, w);
    pack_w2_kernel<<<dim3(2704, LMAX + 1), 256>>>();
    so3_v6_kernel<<<3640, 256>>>(x, out);
}